// round 2
// baseline (speedup 1.0000x reference)
#include <cuda_runtime.h>
#include <cstdint>

#define S 4096
#define HH 64
#define WW 64

// ---------------- scratch (no allocations allowed) ----------------
__device__ float g_hqkv[4 * 96 * S];   // [n][96][s]: q(0-31) k(32-63) v(64-95)
__device__ float g_mkv [4 * 64 * S];   // [n][64][s]: mk(0-31) mv(32-63)
__device__ float g_Z2  [4 * 64 * S];   // [n][64][s]: Zh(0-31) Zm(32-63)
__device__ float g_Zp  [4 * 32 * S];   // [n][32][s]: after Wz
__device__ float g_conv[4 * 192 * S];  // [n][192][s]: conv3x3 output

// ---------------- 1x1 projection: out[n][co][s] = W[co][ci] . in[n][ci][s] + b[co]
template <int CI, int CO>
__global__ __launch_bounds__(256)
void proj_kernel(const float* __restrict__ in, const float* __restrict__ W,
                 const float* __restrict__ b, float* __restrict__ out) {
    __shared__ float Ws[CO * CI];
    int tid = threadIdx.x;
    for (int l = tid; l < CO * CI; l += 256) Ws[l] = W[l];
    __syncthreads();
    int n = blockIdx.y;
    int s = blockIdx.x * 256 + tid;
    float x[CI];
#pragma unroll
    for (int ci = 0; ci < CI; ci++) x[ci] = in[((size_t)n * CI + ci) * S + s];
#pragma unroll 1
    for (int cb = 0; cb < CO; cb += 8) {
        float acc[8];
#pragma unroll
        for (int j = 0; j < 8; j++) acc[j] = b[cb + j];
#pragma unroll
        for (int ci = 0; ci < CI; ci++) {
            float xv = x[ci];
#pragma unroll
            for (int j = 0; j < 8; j++) acc[j] = fmaf(Ws[(cb + j) * CI + ci], xv, acc[j]);
        }
#pragma unroll
        for (int j = 0; j < 8; j++) out[((size_t)n * CO + cb + j) * S + s] = acc[j];
    }
}

// ---------------- flash attention: d=32, S=4096, 64-query tiles ----------------
// grid: (qtile=64, att=2, n=4); 256 threads; thread (ty=tid/16, tx=tid%16)
// owns a 4x4 score tile and 4 rows x 2 d-cols of the output accumulator.
__global__ __launch_bounds__(256)
void attn_kernel(const float* __restrict__ hqkv, const float* __restrict__ mkv,
                 float* __restrict__ Z2) {
    __shared__ float Qs[32][64];
    __shared__ float Ks[32][64];
    __shared__ float Vst[64][34];   // [key][d], stride 34 (float2-aligned, low conflict)
    __shared__ float Ps[64][64];    // probabilities; reused as output stage

    int tid = threadIdx.x;
    int n = blockIdx.z, att = blockIdx.y;
    int q0 = blockIdx.x * 64;

    const float* Q = hqkv + (size_t)n * 96 * S;                       // hq
    const float* K = (att == 0) ? hqkv + ((size_t)n * 96 + 32) * S    // hk
                                : mkv  + ((size_t)n * 64 +  0) * S;   // mk
    const float* V = (att == 0) ? hqkv + ((size_t)n * 96 + 64) * S    // hv
                                : mkv  + ((size_t)n * 64 + 32) * S;   // mv
    float* Out = Z2 + ((size_t)n * 64 + att * 32) * S;

    const float scale = 0.17677669529663687f; // 1/sqrt(32)
    for (int l = tid; l < 2048; l += 256) {
        int d = l >> 6, sl = l & 63;
        Qs[d][sl] = Q[(size_t)d * S + q0 + sl] * scale;
    }

    int tx = tid & 15, ty = tid >> 4;
    float m_i[4], l_i[4], accx[4], accy[4];
#pragma unroll
    for (int r = 0; r < 4; r++) { m_i[r] = -1e30f; l_i[r] = 0.f; accx[r] = 0.f; accy[r] = 0.f; }

    for (int kt = 0; kt < 64; kt++) {
        int kb = kt * 64;
        __syncthreads();  // prev PV done before K/V/Ps buffers change
        for (int l = tid; l < 2048; l += 256) {
            int d = l >> 6, sl = l & 63;
            float kv = K[(size_t)d * S + kb + sl];
            float vv = V[(size_t)d * S + kb + sl];
            Ks[d][sl] = kv;
            Vst[sl][d] = vv;
        }
        __syncthreads();

        // ---- QK^T: 4x4 register tile over d=32
        float sc[4][4];
#pragma unroll
        for (int r = 0; r < 4; r++)
#pragma unroll
            for (int c = 0; c < 4; c++) sc[r][c] = 0.f;
#pragma unroll
        for (int d = 0; d < 32; d++) {
            float4 q4 = *(const float4*)&Qs[d][ty * 4];
            float4 k4 = *(const float4*)&Ks[d][tx * 4];
            sc[0][0] = fmaf(q4.x, k4.x, sc[0][0]); sc[0][1] = fmaf(q4.x, k4.y, sc[0][1]);
            sc[0][2] = fmaf(q4.x, k4.z, sc[0][2]); sc[0][3] = fmaf(q4.x, k4.w, sc[0][3]);
            sc[1][0] = fmaf(q4.y, k4.x, sc[1][0]); sc[1][1] = fmaf(q4.y, k4.y, sc[1][1]);
            sc[1][2] = fmaf(q4.y, k4.z, sc[1][2]); sc[1][3] = fmaf(q4.y, k4.w, sc[1][3]);
            sc[2][0] = fmaf(q4.z, k4.x, sc[2][0]); sc[2][1] = fmaf(q4.z, k4.y, sc[2][1]);
            sc[2][2] = fmaf(q4.z, k4.z, sc[2][2]); sc[2][3] = fmaf(q4.z, k4.w, sc[2][3]);
            sc[3][0] = fmaf(q4.w, k4.x, sc[3][0]); sc[3][1] = fmaf(q4.w, k4.y, sc[3][1]);
            sc[3][2] = fmaf(q4.w, k4.z, sc[3][2]); sc[3][3] = fmaf(q4.w, k4.w, sc[3][3]);
        }

        // ---- online softmax (row groups live in aligned 16-lane shuffle groups)
#pragma unroll
        for (int r = 0; r < 4; r++) {
            float mm = fmaxf(fmaxf(sc[r][0], sc[r][1]), fmaxf(sc[r][2], sc[r][3]));
            mm = fmaxf(mm, __shfl_xor_sync(0xffffffffu, mm, 1));
            mm = fmaxf(mm, __shfl_xor_sync(0xffffffffu, mm, 2));
            mm = fmaxf(mm, __shfl_xor_sync(0xffffffffu, mm, 4));
            mm = fmaxf(mm, __shfl_xor_sync(0xffffffffu, mm, 8));
            float mn = fmaxf(m_i[r], mm);
            float sca = __expf(m_i[r] - mn);
            m_i[r] = mn;
            float lt = 0.f;
#pragma unroll
            for (int c = 0; c < 4; c++) { sc[r][c] = __expf(sc[r][c] - mn); lt += sc[r][c]; }
            lt += __shfl_xor_sync(0xffffffffu, lt, 1);
            lt += __shfl_xor_sync(0xffffffffu, lt, 2);
            lt += __shfl_xor_sync(0xffffffffu, lt, 4);
            lt += __shfl_xor_sync(0xffffffffu, lt, 8);
            l_i[r] = l_i[r] * sca + lt;
            accx[r] *= sca; accy[r] *= sca;
            *(float4*)&Ps[4 * ty + r][4 * tx] = make_float4(sc[r][0], sc[r][1], sc[r][2], sc[r][3]);
        }
        __syncthreads();

        // ---- O += P @ V : rows 4ty..4ty+3, d-cols {2tx, 2tx+1}
#pragma unroll 4
        for (int j = 0; j < 64; j += 4) {
            float2 v0 = *(const float2*)&Vst[j + 0][2 * tx];
            float2 v1 = *(const float2*)&Vst[j + 1][2 * tx];
            float2 v2 = *(const float2*)&Vst[j + 2][2 * tx];
            float2 v3 = *(const float2*)&Vst[j + 3][2 * tx];
#pragma unroll
            for (int r = 0; r < 4; r++) {
                float4 p = *(const float4*)&Ps[4 * ty + r][j];
                accx[r] = fmaf(p.x, v0.x, accx[r]);
                accx[r] = fmaf(p.y, v1.x, accx[r]);
                accx[r] = fmaf(p.z, v2.x, accx[r]);
                accx[r] = fmaf(p.w, v3.x, accx[r]);
                accy[r] = fmaf(p.x, v0.y, accy[r]);
                accy[r] = fmaf(p.y, v1.y, accy[r]);
                accy[r] = fmaf(p.z, v2.y, accy[r]);
                accy[r] = fmaf(p.w, v3.y, accy[r]);
            }
        }
    }

    // ---- epilogue: normalize, stage [d][sl] in smem, coalesced store
    __syncthreads();
    float* Osm = &Ps[0][0];
#pragma unroll
    for (int r = 0; r < 4; r++) {
        float inv = 1.0f / l_i[r];
        Osm[(2 * tx + 0) * 64 + 4 * ty + r] = accx[r] * inv;
        Osm[(2 * tx + 1) * 64 + 4 * ty + r] = accy[r] * inv;
    }
    __syncthreads();
    for (int l = tid; l < 2048; l += 256) {
        int d = l >> 6, sl = l & 63;
        Out[(size_t)d * S + q0 + sl] = Osm[d * 64 + sl];
    }
}

// ---------------- 3x3 conv, SAME pad: in = concat(Zp[32], h[64]), out 192 ch
// grid: (16 spatial tiles of 16x16, 6 co-groups of 32, n). 256 threads:
// thread = (cosub: 8 co) x (4 consecutive x-pixels).
__global__ __launch_bounds__(256)
void conv3x3_kernel(const float* __restrict__ Zin, const float* __restrict__ hin,
                    const float* __restrict__ Wo, const float* __restrict__ bo,
                    float* __restrict__ out) {
    __shared__ float patch[16][18 * 18];      // [ci][(yy)*18+xx]
    __shared__ float Wsm[16 * 9 * 32];        // [(ci*9+k)*32 + co]

    int tid = threadIdx.x;
    int n = blockIdx.z, cog = blockIdx.y, tile = blockIdx.x;
    int ty0 = (tile >> 2) * 16, tx0 = (tile & 3) * 16;
    int cosub = tid & 3, pg = tid >> 2;
    int py = pg >> 2, px = (pg & 3) * 4;
    int co0 = cosub * 8;

    float acc[32];
#pragma unroll
    for (int i = 0; i < 32; i++) acc[i] = 0.f;

    for (int cig = 0; cig < 6; cig++) {
        __syncthreads();
        // input patch (zero-padded borders)
        for (int l = tid; l < 16 * 324; l += 256) {
            int ci = l / 324, rem = l - ci * 324;
            int yy = rem / 18 + ty0 - 1, xx = rem % 18 + tx0 - 1;
            float v = 0.f;
            if (yy >= 0 && yy < HH && xx >= 0 && xx < WW) {
                int cg = cig * 16 + ci;
                v = (cg < 32) ? Zin[((size_t)n * 32 + cg) * S + yy * WW + xx]
                              : hin[((size_t)n * 64 + (cg - 32)) * S + yy * WW + xx];
            }
            patch[ci][rem] = v;
        }
        // weights reorganized to [(ci*9+k)*32 + co]
        for (int l = tid; l < 16 * 9 * 32; l += 256) {
            int co = l & 31, rest = l >> 5;
            int ci = rest / 9, k = rest - ci * 9;
            Wsm[l] = Wo[(((size_t)cog * 32 + co) * 96 + cig * 16 + ci) * 9 + k];
        }
        __syncthreads();

        for (int ci = 0; ci < 16; ci++) {
#pragma unroll
            for (int kh = 0; kh < 3; kh++) {
                float in6[6];
                const float* prow = &patch[ci][(py + kh) * 18 + px];
#pragma unroll
                for (int u = 0; u < 6; u++) in6[u] = prow[u];
#pragma unroll
                for (int kw = 0; kw < 3; kw++) {
                    const float4 wa = *(const float4*)&Wsm[(ci * 9 + kh * 3 + kw) * 32 + co0];
                    const float4 wb = *(const float4*)&Wsm[(ci * 9 + kh * 3 + kw) * 32 + co0 + 4];
#pragma unroll
                    for (int i = 0; i < 4; i++) {
                        float xv = in6[kw + i];
                        acc[i * 8 + 0] = fmaf(wa.x, xv, acc[i * 8 + 0]);
                        acc[i * 8 + 1] = fmaf(wa.y, xv, acc[i * 8 + 1]);
                        acc[i * 8 + 2] = fmaf(wa.z, xv, acc[i * 8 + 2]);
                        acc[i * 8 + 3] = fmaf(wa.w, xv, acc[i * 8 + 3]);
                        acc[i * 8 + 4] = fmaf(wb.x, xv, acc[i * 8 + 4]);
                        acc[i * 8 + 5] = fmaf(wb.y, xv, acc[i * 8 + 5]);
                        acc[i * 8 + 6] = fmaf(wb.z, xv, acc[i * 8 + 6]);
                        acc[i * 8 + 7] = fmaf(wb.w, xv, acc[i * 8 + 7]);
                    }
                }
            }
        }
    }

    int y = ty0 + py, xb = tx0 + px;
#pragma unroll
    for (int j = 0; j < 8; j++) {
        int co = cog * 32 + co0 + j;
        float bb = bo[co];
#pragma unroll
        for (int i = 0; i < 4; i++)
            out[((size_t)n * 192 + co) * S + y * WW + xb + i] = acc[i * 8 + j] + bb;
    }
}

// ---------------- gates: i,g,o -> h_next, m_next ----------------
__global__ __launch_bounds__(256)
void gates_kernel(const float* __restrict__ conv, const float* __restrict__ m,
                  float* __restrict__ out) {
    int idx = blockIdx.x * 256 + threadIdx.x;       // over N*64*S = 1,048,576
    int n = idx >> 18;                              // 64*4096 = 262144 = 2^18
    int rem = idx & 262143;
    size_t base = (size_t)n * 192 * S;
    float iv = conv[base + rem];
    float gv = conv[base + 64 * S + rem];
    float ov = conv[base + 128 * S + rem];
    float mi = m[idx];
    float si = 1.0f / (1.0f + __expf(-iv));
    float gg = tanhf(gv);
    float so = 1.0f / (1.0f + __expf(-ov));
    float mn = si * gg + (1.0f - si) * mi;
    float hn = so * mn;
    out[idx] = hn;
    out[1048576 + idx] = mn;
}

// ---------------- launch ----------------
extern "C" void kernel_launch(void* const* d_in, const int* in_sizes, int n_in,
                              void* d_out, int out_size) {
    const float* h  = (const float*)d_in[0];
    const float* m  = (const float*)d_in[1];
    const float* Wh = (const float*)d_in[2];
    const float* bh = (const float*)d_in[3];
    const float* Wm = (const float*)d_in[4];
    const float* bm = (const float*)d_in[5];
    const float* Wz = (const float*)d_in[6];
    const float* bz = (const float*)d_in[7];
    const float* Wo = (const float*)d_in[8];
    const float* bo = (const float*)d_in[9];
    float* out = (float*)d_out;

    float *pHqkv, *pMkv, *pZ2, *pZp, *pConv;
    cudaGetSymbolAddress((void**)&pHqkv, g_hqkv);
    cudaGetSymbolAddress((void**)&pMkv,  g_mkv);
    cudaGetSymbolAddress((void**)&pZ2,   g_Z2);
    cudaGetSymbolAddress((void**)&pZp,   g_Zp);
    cudaGetSymbolAddress((void**)&pConv, g_conv);

    dim3 pj(16, 4);
    proj_kernel<64, 96><<<pj, 256>>>(h, Wh, bh, pHqkv);
    proj_kernel<64, 64><<<pj, 256>>>(m, Wm, bm, pMkv);
    attn_kernel<<<dim3(64, 2, 4), 256>>>(pHqkv, pMkv, pZ2);
    proj_kernel<64, 32><<<pj, 256>>>(pZ2, Wz, bz, pZp);
    conv3x3_kernel<<<dim3(16, 6, 4), 256>>>(pZp, h, Wo, bo, pConv);
    gates_kernel<<<4096, 256>>>(pConv, m, out);
}

// round 5
// speedup vs baseline: 1.9100x; 1.9100x over previous
#include <cuda_runtime.h>
#include <cuda_bf16.h>
#include <cstdint>

#define S 4096
#define HH 64
#define WW 64

// ---------------- scratch (no allocations allowed) ----------------
__device__ float g_hqkv[4 * 96 * S];   // [n][96][s]: q(0-31) k(32-63) v(64-95)
__device__ float g_mkv [4 * 64 * S];   // [n][64][s]: mk(0-31) mv(32-63)
__device__ float g_Z2  [4 * 64 * S];   // [n][64][s]: Zh(0-31) Zm(32-63)
__device__ float g_Zp  [4 * 32 * S];   // [n][32][s]: after Wz
__device__ float g_conv[4 * 192 * S];  // [n][192][s]: conv3x3 output

// ---------------- 1x1 projection ----------------
template <int CI, int CO>
__global__ __launch_bounds__(256)
void proj_kernel(const float* __restrict__ in, const float* __restrict__ W,
                 const float* __restrict__ b, float* __restrict__ out) {
    __shared__ float Ws[CO * CI];
    int tid = threadIdx.x;
    for (int l = tid; l < CO * CI; l += 256) Ws[l] = W[l];
    __syncthreads();
    int n = blockIdx.y;
    int s = blockIdx.x * 256 + tid;
    float x[CI];
#pragma unroll
    for (int ci = 0; ci < CI; ci++) x[ci] = in[((size_t)n * CI + ci) * S + s];
#pragma unroll 1
    for (int cb = 0; cb < CO; cb += 8) {
        float acc[8];
#pragma unroll
        for (int j = 0; j < 8; j++) acc[j] = b[cb + j];
#pragma unroll
        for (int ci = 0; ci < CI; ci++) {
            float xv = x[ci];
#pragma unroll
            for (int j = 0; j < 8; j++) acc[j] = fmaf(Ws[(cb + j) * CI + ci], xv, acc[j]);
        }
#pragma unroll
        for (int j = 0; j < 8; j++) out[((size_t)n * CO + cb + j) * S + s] = acc[j];
    }
}

// ---------------- mma.sync helpers (base-ISA, sm_80+) ----------------
__device__ __forceinline__ void mma16816(float* c, const uint32_t* a, uint32_t b0, uint32_t b1) {
    asm volatile(
        "mma.sync.aligned.m16n8k16.row.col.f32.bf16.bf16.f32 "
        "{%0,%1,%2,%3}, {%4,%5,%6,%7}, {%8,%9}, {%0,%1,%2,%3};"
        : "+f"(c[0]), "+f"(c[1]), "+f"(c[2]), "+f"(c[3])
        : "r"(a[0]), "r"(a[1]), "r"(a[2]), "r"(a[3]), "r"(b0), "r"(b1));
}
__device__ __forceinline__ uint32_t packbf(float lo, float hi) {
    uint32_t r;
    asm("cvt.rn.bf16x2.f32 %0, %2, %1;" : "=r"(r) : "f"(lo), "f"(hi));
    return r;
}

// ---------------- flash attention on mma.sync ----------------
// grid (32 qtiles, 2 att, 4 n), 128 threads (4 warps).
// Warp w owns query rows 32w..32w+31 (two m16 tiles). Key loop: 64-key chunks.
// smem (uint32 words):
//   Qs: 128 rows x 20 words (80B stride, 32 bf16 d + pad)  [0,2560)
//   Ks:  64 rows x 20 words                                [2560,3840)
//   Vs:  32 d-rows x 35 words (140B stride, 64 bf16 keys)  [3840,4960)
//   Osm overlay for epilogue: 32 x 130 f32 = 4160 words    [0,4160)
#define SMW 4960

__global__ __launch_bounds__(128)
void attn_mma_kernel(const float* __restrict__ hqkv, const float* __restrict__ mkv,
                     float* __restrict__ Z2) {
    __shared__ uint32_t smw[SMW];
    uint32_t* Qsw = smw;
    uint32_t* Ksw = smw + 2560;
    uint32_t* Vsw = smw + 3840;
    __nv_bfloat16* Qh = (__nv_bfloat16*)Qsw;
    __nv_bfloat16* Kh = (__nv_bfloat16*)Ksw;

    int tid = threadIdx.x;
    int w = tid >> 5, lane = tid & 31;
    int lq = lane >> 2, lj = lane & 3;
    int n = blockIdx.z, att = blockIdx.y;
    int q0 = blockIdx.x * 128;

    const float* Q = hqkv + (size_t)n * 96 * S;
    const float* K = (att == 0) ? hqkv + ((size_t)n * 96 + 32) * S
                                : mkv  + ((size_t)n * 64 +  0) * S;
    const float* V = (att == 0) ? hqkv + ((size_t)n * 96 + 64) * S
                                : mkv  + ((size_t)n * 64 + 32) * S;
    float* Out = Z2 + ((size_t)n * 64 + att * 32) * S;

    // ---- stage Q (bf16, pre-scaled): Qs[q][d], 40 halves/row
    const float scale = 0.17677669529663687f; // 1/sqrt(32)
    for (int i = tid; i < 4096; i += 128) {
        int d = i >> 7, q = i & 127;
        Qh[q * 40 + d] = __float2bfloat16(Q[(size_t)d * S + q0 + q] * scale);
    }
    __syncthreads();

    // ---- Q A-fragments (persistent): qa[mtile][kstep][4]
    uint32_t qa[2][2][4];
#pragma unroll
    for (int mt = 0; mt < 2; mt++) {
        int r0 = 32 * w + 16 * mt + lq;
#pragma unroll
        for (int ks = 0; ks < 2; ks++) {
            qa[mt][ks][0] = Qsw[r0 * 20 + ks * 8 + lj];
            qa[mt][ks][1] = Qsw[(r0 + 8) * 20 + ks * 8 + lj];
            qa[mt][ks][2] = Qsw[r0 * 20 + ks * 8 + lj + 4];
            qa[mt][ks][3] = Qsw[(r0 + 8) * 20 + ks * 8 + lj + 4];
        }
    }

    float oacc[2][4][4];   // [mtile][d-tile][frag]
#pragma unroll
    for (int mt = 0; mt < 2; mt++)
#pragma unroll
        for (int nt = 0; nt < 4; nt++)
#pragma unroll
            for (int r = 0; r < 4; r++) oacc[mt][nt][r] = 0.f;
    float l_acc[4] = {0.f, 0.f, 0.f, 0.f};   // rows: [mt*2 + (0: t/4, 1: t/4+8)]

    for (int kt = 0; kt < 64; kt++) {
        int kb = kt * 64;
        __syncthreads();   // prior chunk's MMAs done before overwrite
        // K chunk -> Ks[key][d]
        for (int i = tid; i < 2048; i += 128) {
            int d = i >> 6, k = i & 63;
            Kh[k * 40 + d] = __float2bfloat16(K[(size_t)d * S + kb + k]);
        }
        // V chunk -> Vs[d][key] (packed bf16x2)
        for (int i = tid; i < 1024; i += 128) {
            int d = i >> 5, kp = i & 31;
            float2 v2 = *(const float2*)&V[(size_t)d * S + kb + 2 * kp];
            Vsw[d * 35 + kp] = packbf(v2.x, v2.y);
        }
        __syncthreads();

        // ---- QK + softmax + pack P into A-fragment layout
        uint32_t p[2][4][4];   // [mtile][kstep(16 keys)][4 regs]
#pragma unroll
        for (int mt = 0; mt < 2; mt++) {
            float rs0 = 0.f, rs1 = 0.f;
#pragma unroll
            for (int nn = 0; nn < 8; nn++) {    // key n-tiles of 8
                float c[4] = {0.f, 0.f, 0.f, 0.f};
#pragma unroll
                for (int ks = 0; ks < 2; ks++) {
                    int bw = (nn * 8 + lq) * 20 + ks * 8 + lj;
                    mma16816(c, qa[mt][ks], Ksw[bw], Ksw[bw + 4]);
                }
                float e0 = __expf(c[0]), e1 = __expf(c[1]);
                float e2 = __expf(c[2]), e3 = __expf(c[3]);
                rs0 += e0 + e1; rs1 += e2 + e3;
                int kk = nn >> 1, half = (nn & 1) * 2;
                p[mt][kk][half + 0] = packbf(e0, e1);
                p[mt][kk][half + 1] = packbf(e2, e3);
            }
            rs0 += __shfl_xor_sync(0xffffffffu, rs0, 1);
            rs0 += __shfl_xor_sync(0xffffffffu, rs0, 2);
            rs1 += __shfl_xor_sync(0xffffffffu, rs1, 1);
            rs1 += __shfl_xor_sync(0xffffffffu, rs1, 2);
            l_acc[mt * 2 + 0] += rs0;
            l_acc[mt * 2 + 1] += rs1;
        }

        // ---- O += P @ V
#pragma unroll
        for (int nt = 0; nt < 4; nt++) {
#pragma unroll
            for (int kk = 0; kk < 4; kk++) {
                int bw = (nt * 8 + lq) * 35 + kk * 8 + lj;
                uint32_t b0 = Vsw[bw], b1 = Vsw[bw + 4];
                mma16816(oacc[0][nt], p[0][kk], b0, b1);
                mma16816(oacc[1][nt], p[1][kk], b0, b1);
            }
        }
    }

    // ---- epilogue: normalize, stage Osm[d][q] (130 f32 stride), coalesced store
    __syncthreads();   // all warps done reading Vs before overlay
    float* Osm = (float*)smw;
    float inv[4];
#pragma unroll
    for (int r = 0; r < 4; r++) inv[r] = 1.0f / l_acc[r];
#pragma unroll
    for (int mt = 0; mt < 2; mt++) {
        int r0 = 32 * w + 16 * mt + lq;
#pragma unroll
        for (int nt = 0; nt < 4; nt++) {
            int d0 = nt * 8 + 2 * lj;
            Osm[(d0 + 0) * 130 + r0]     = oacc[mt][nt][0] * inv[mt * 2];
            Osm[(d0 + 1) * 130 + r0]     = oacc[mt][nt][1] * inv[mt * 2];
            Osm[(d0 + 0) * 130 + r0 + 8] = oacc[mt][nt][2] * inv[mt * 2 + 1];
            Osm[(d0 + 1) * 130 + r0 + 8] = oacc[mt][nt][3] * inv[mt * 2 + 1];
        }
    }
    __syncthreads();
    for (int i = tid; i < 4096; i += 128) {
        int d = i >> 7, q = i & 127;
        Out[(size_t)d * S + q0 + q] = Osm[d * 130 + q];
    }
}

// ---------------- 3x3 conv (unchanged) ----------------
__global__ __launch_bounds__(256)
void conv3x3_kernel(const float* __restrict__ Zin, const float* __restrict__ hin,
                    const float* __restrict__ Wo, const float* __restrict__ bo,
                    float* __restrict__ out) {
    __shared__ float patch[16][18 * 18];
    __shared__ float Wsm[16 * 9 * 32];

    int tid = threadIdx.x;
    int n = blockIdx.z, cog = blockIdx.y, tile = blockIdx.x;
    int ty0 = (tile >> 2) * 16, tx0 = (tile & 3) * 16;
    int cosub = tid & 3, pg = tid >> 2;
    int py = pg >> 2, px = (pg & 3) * 4;
    int co0 = cosub * 8;

    float acc[32];
#pragma unroll
    for (int i = 0; i < 32; i++) acc[i] = 0.f;

    for (int cig = 0; cig < 6; cig++) {
        __syncthreads();
        for (int l = tid; l < 16 * 324; l += 256) {
            int ci = l / 324, rem = l - ci * 324;
            int yy = rem / 18 + ty0 - 1, xx = rem % 18 + tx0 - 1;
            float v = 0.f;
            if (yy >= 0 && yy < HH && xx >= 0 && xx < WW) {
                int cg = cig * 16 + ci;
                v = (cg < 32) ? Zin[((size_t)n * 32 + cg) * S + yy * WW + xx]
                              : hin[((size_t)n * 64 + (cg - 32)) * S + yy * WW + xx];
            }
            patch[ci][rem] = v;
        }
        for (int l = tid; l < 16 * 9 * 32; l += 256) {
            int co = l & 31, rest = l >> 5;
            int ci = rest / 9, k = rest - ci * 9;
            Wsm[l] = Wo[(((size_t)cog * 32 + co) * 96 + cig * 16 + ci) * 9 + k];
        }
        __syncthreads();

        for (int ci = 0; ci < 16; ci++) {
#pragma unroll
            for (int kh = 0; kh < 3; kh++) {
                float in6[6];
                const float* prow = &patch[ci][(py + kh) * 18 + px];
#pragma unroll
                for (int u = 0; u < 6; u++) in6[u] = prow[u];
#pragma unroll
                for (int kw = 0; kw < 3; kw++) {
                    const float4 wa = *(const float4*)&Wsm[(ci * 9 + kh * 3 + kw) * 32 + co0];
                    const float4 wb = *(const float4*)&Wsm[(ci * 9 + kh * 3 + kw) * 32 + co0 + 4];
#pragma unroll
                    for (int i = 0; i < 4; i++) {
                        float xv = in6[kw + i];
                        acc[i * 8 + 0] = fmaf(wa.x, xv, acc[i * 8 + 0]);
                        acc[i * 8 + 1] = fmaf(wa.y, xv, acc[i * 8 + 1]);
                        acc[i * 8 + 2] = fmaf(wa.z, xv, acc[i * 8 + 2]);
                        acc[i * 8 + 3] = fmaf(wa.w, xv, acc[i * 8 + 3]);
                        acc[i * 8 + 4] = fmaf(wb.x, xv, acc[i * 8 + 4]);
                        acc[i * 8 + 5] = fmaf(wb.y, xv, acc[i * 8 + 5]);
                        acc[i * 8 + 6] = fmaf(wb.z, xv, acc[i * 8 + 6]);
                        acc[i * 8 + 7] = fmaf(wb.w, xv, acc[i * 8 + 7]);
                    }
                }
            }
        }
    }

    int y = ty0 + py, xb = tx0 + px;
#pragma unroll
    for (int j = 0; j < 8; j++) {
        int co = cog * 32 + co0 + j;
        float bb = bo[co];
#pragma unroll
        for (int i = 0; i < 4; i++)
            out[((size_t)n * 192 + co) * S + y * WW + xb + i] = acc[i * 8 + j] + bb;
    }
}

// ---------------- gates (unchanged) ----------------
__global__ __launch_bounds__(256)
void gates_kernel(const float* __restrict__ conv, const float* __restrict__ m,
                  float* __restrict__ out) {
    int idx = blockIdx.x * 256 + threadIdx.x;
    int n = idx >> 18;
    int rem = idx & 262143;
    size_t base = (size_t)n * 192 * S;
    float iv = conv[base + rem];
    float gv = conv[base + 64 * S + rem];
    float ov = conv[base + 128 * S + rem];
    float mi = m[idx];
    float si = 1.0f / (1.0f + __expf(-iv));
    float gg = tanhf(gv);
    float so = 1.0f / (1.0f + __expf(-ov));
    float mn = si * gg + (1.0f - si) * mi;
    float hn = so * mn;
    out[idx] = hn;
    out[1048576 + idx] = mn;
}

// ---------------- launch ----------------
extern "C" void kernel_launch(void* const* d_in, const int* in_sizes, int n_in,
                              void* d_out, int out_size) {
    const float* h  = (const float*)d_in[0];
    const float* m  = (const float*)d_in[1];
    const float* Wh = (const float*)d_in[2];
    const float* bh = (const float*)d_in[3];
    const float* Wm = (const float*)d_in[4];
    const float* bm = (const float*)d_in[5];
    const float* Wz = (const float*)d_in[6];
    const float* bz = (const float*)d_in[7];
    const float* Wo = (const float*)d_in[8];
    const float* bo = (const float*)d_in[9];
    float* out = (float*)d_out;

    float *pHqkv, *pMkv, *pZ2, *pZp, *pConv;
    cudaGetSymbolAddress((void**)&pHqkv, g_hqkv);
    cudaGetSymbolAddress((void**)&pMkv,  g_mkv);
    cudaGetSymbolAddress((void**)&pZ2,   g_Z2);
    cudaGetSymbolAddress((void**)&pZp,   g_Zp);
    cudaGetSymbolAddress((void**)&pConv, g_conv);

    dim3 pj(16, 4);
    proj_kernel<64, 96><<<pj, 256>>>(h, Wh, bh, pHqkv);
    proj_kernel<64, 64><<<pj, 256>>>(m, Wm, bm, pMkv);
    attn_mma_kernel<<<dim3(32, 2, 4), 128>>>(pHqkv, pMkv, pZ2);
    proj_kernel<64, 32><<<pj, 256>>>(pZ2, Wz, bz, pZp);
    conv3x3_kernel<<<dim3(16, 6, 4), 256>>>(pZp, h, Wo, bo, pConv);
    gates_kernel<<<4096, 256>>>(pConv, m, out);
}

// round 6
// speedup vs baseline: 2.5526x; 1.3364x over previous
#include <cuda_runtime.h>
#include <cuda_bf16.h>
#include <cstdint>

#define S 4096
#define HH 64
#define WW 64

// ---------------- scratch (no allocations allowed) ----------------
__device__ float g_hqkv[4 * 96 * S];
__device__ float g_mkv [4 * 64 * S];
__device__ float g_Z2  [4 * 64 * S];
__device__ float g_Zp  [4 * 32 * S];
__device__ float g_conv[4 * 192 * S];

// ---------------- 1x1 projection: 32-co tile per block, 128-s tile ----------------
template <int CI, int COTOT>
__global__ __launch_bounds__(128)
void proj_kernel(const float* __restrict__ in, const float* __restrict__ W,
                 const float* __restrict__ b, float* __restrict__ out) {
    __shared__ float Ws[32 * CI];
    int tid = threadIdx.x;
    int co0 = blockIdx.y * 32;
    for (int l = tid; l < 32 * CI; l += 128) Ws[l] = W[co0 * CI + l];
    __syncthreads();
    int n = blockIdx.z;
    int s = blockIdx.x * 128 + tid;
    float x[CI];
#pragma unroll
    for (int ci = 0; ci < CI; ci++) x[ci] = in[((size_t)n * CI + ci) * S + s];
#pragma unroll 1
    for (int cb = 0; cb < 32; cb += 8) {
        float acc[8];
#pragma unroll
        for (int j = 0; j < 8; j++) acc[j] = b[co0 + cb + j];
#pragma unroll
        for (int ci = 0; ci < CI; ci++) {
            float xv = x[ci];
#pragma unroll
            for (int j = 0; j < 8; j++) acc[j] = fmaf(Ws[(cb + j) * CI + ci], xv, acc[j]);
        }
#pragma unroll
        for (int j = 0; j < 8; j++) out[((size_t)n * COTOT + co0 + cb + j) * S + s] = acc[j];
    }
}

// ---------------- mma.sync helpers (base-ISA, sm_80+) ----------------
__device__ __forceinline__ void mma16816(float* c, const uint32_t* a, uint32_t b0, uint32_t b1) {
    asm volatile(
        "mma.sync.aligned.m16n8k16.row.col.f32.bf16.bf16.f32 "
        "{%0,%1,%2,%3}, {%4,%5,%6,%7}, {%8,%9}, {%0,%1,%2,%3};"
        : "+f"(c[0]), "+f"(c[1]), "+f"(c[2]), "+f"(c[3])
        : "r"(a[0]), "r"(a[1]), "r"(a[2]), "r"(a[3]), "r"(b0), "r"(b1));
}
__device__ __forceinline__ void mma1688t(float* c, const uint32_t* a, uint32_t b0, uint32_t b1) {
    asm volatile(
        "mma.sync.aligned.m16n8k8.row.col.f32.tf32.tf32.f32 "
        "{%0,%1,%2,%3}, {%4,%5,%6,%7}, {%8,%9}, {%0,%1,%2,%3};"
        : "+f"(c[0]), "+f"(c[1]), "+f"(c[2]), "+f"(c[3])
        : "r"(a[0]), "r"(a[1]), "r"(a[2]), "r"(a[3]), "r"(b0), "r"(b1));
}
__device__ __forceinline__ uint32_t packbf(float lo, float hi) {
    uint32_t r;
    asm("cvt.rn.bf16x2.f32 %0, %2, %1;" : "=r"(r) : "f"(lo), "f"(hi));
    return r;
}
__device__ __forceinline__ uint32_t f2tf32(float f) {
    uint32_t r;
    asm("cvt.rna.tf32.f32 %0, %1;" : "=r"(r) : "f"(f));
    return r;
}

// ---------------- flash attention on mma.sync (unchanged from R5) ----------------
#define SMW 4960
__global__ __launch_bounds__(128)
void attn_mma_kernel(const float* __restrict__ hqkv, const float* __restrict__ mkv,
                     float* __restrict__ Z2) {
    __shared__ uint32_t smw[SMW];
    uint32_t* Qsw = smw;
    uint32_t* Ksw = smw + 2560;
    uint32_t* Vsw = smw + 3840;
    __nv_bfloat16* Qh = (__nv_bfloat16*)Qsw;
    __nv_bfloat16* Kh = (__nv_bfloat16*)Ksw;

    int tid = threadIdx.x;
    int w = tid >> 5, lane = tid & 31;
    int lq = lane >> 2, lj = lane & 3;
    int n = blockIdx.z, att = blockIdx.y;
    int q0 = blockIdx.x * 128;

    const float* Q = hqkv + (size_t)n * 96 * S;
    const float* K = (att == 0) ? hqkv + ((size_t)n * 96 + 32) * S
                                : mkv  + ((size_t)n * 64 +  0) * S;
    const float* V = (att == 0) ? hqkv + ((size_t)n * 96 + 64) * S
                                : mkv  + ((size_t)n * 64 + 32) * S;
    float* Out = Z2 + ((size_t)n * 64 + att * 32) * S;

    const float scale = 0.17677669529663687f;
    for (int i = tid; i < 4096; i += 128) {
        int d = i >> 7, q = i & 127;
        Qh[q * 40 + d] = __float2bfloat16(Q[(size_t)d * S + q0 + q] * scale);
    }
    __syncthreads();

    uint32_t qa[2][2][4];
#pragma unroll
    for (int mt = 0; mt < 2; mt++) {
        int r0 = 32 * w + 16 * mt + lq;
#pragma unroll
        for (int ks = 0; ks < 2; ks++) {
            qa[mt][ks][0] = Qsw[r0 * 20 + ks * 8 + lj];
            qa[mt][ks][1] = Qsw[(r0 + 8) * 20 + ks * 8 + lj];
            qa[mt][ks][2] = Qsw[r0 * 20 + ks * 8 + lj + 4];
            qa[mt][ks][3] = Qsw[(r0 + 8) * 20 + ks * 8 + lj + 4];
        }
    }

    float oacc[2][4][4];
#pragma unroll
    for (int mt = 0; mt < 2; mt++)
#pragma unroll
        for (int nt = 0; nt < 4; nt++)
#pragma unroll
            for (int r = 0; r < 4; r++) oacc[mt][nt][r] = 0.f;
    float l_acc[4] = {0.f, 0.f, 0.f, 0.f};

    for (int kt = 0; kt < 64; kt++) {
        int kb = kt * 64;
        __syncthreads();
        for (int i = tid; i < 2048; i += 128) {
            int d = i >> 6, k = i & 63;
            Kh[k * 40 + d] = __float2bfloat16(K[(size_t)d * S + kb + k]);
        }
        for (int i = tid; i < 1024; i += 128) {
            int d = i >> 5, kp = i & 31;
            float2 v2 = *(const float2*)&V[(size_t)d * S + kb + 2 * kp];
            Vsw[d * 35 + kp] = packbf(v2.x, v2.y);
        }
        __syncthreads();

        uint32_t p[2][4][4];
#pragma unroll
        for (int mt = 0; mt < 2; mt++) {
            float rs0 = 0.f, rs1 = 0.f;
#pragma unroll
            for (int nn = 0; nn < 8; nn++) {
                float c[4] = {0.f, 0.f, 0.f, 0.f};
#pragma unroll
                for (int ks = 0; ks < 2; ks++) {
                    int bw = (nn * 8 + lq) * 20 + ks * 8 + lj;
                    mma16816(c, qa[mt][ks], Ksw[bw], Ksw[bw + 4]);
                }
                float e0 = __expf(c[0]), e1 = __expf(c[1]);
                float e2 = __expf(c[2]), e3 = __expf(c[3]);
                rs0 += e0 + e1; rs1 += e2 + e3;
                int kk = nn >> 1, half = (nn & 1) * 2;
                p[mt][kk][half + 0] = packbf(e0, e1);
                p[mt][kk][half + 1] = packbf(e2, e3);
            }
            rs0 += __shfl_xor_sync(0xffffffffu, rs0, 1);
            rs0 += __shfl_xor_sync(0xffffffffu, rs0, 2);
            rs1 += __shfl_xor_sync(0xffffffffu, rs1, 1);
            rs1 += __shfl_xor_sync(0xffffffffu, rs1, 2);
            l_acc[mt * 2 + 0] += rs0;
            l_acc[mt * 2 + 1] += rs1;
        }

#pragma unroll
        for (int nt = 0; nt < 4; nt++) {
#pragma unroll
            for (int kk = 0; kk < 4; kk++) {
                int bw = (nt * 8 + lq) * 35 + kk * 8 + lj;
                uint32_t b0 = Vsw[bw], b1 = Vsw[bw + 4];
                mma16816(oacc[0][nt], p[0][kk], b0, b1);
                mma16816(oacc[1][nt], p[1][kk], b0, b1);
            }
        }
    }

    __syncthreads();
    float* Osm = (float*)smw;
    float inv[4];
#pragma unroll
    for (int r = 0; r < 4; r++) inv[r] = 1.0f / l_acc[r];
#pragma unroll
    for (int mt = 0; mt < 2; mt++) {
        int r0 = 32 * w + 16 * mt + lq;
#pragma unroll
        for (int nt = 0; nt < 4; nt++) {
            int d0 = nt * 8 + 2 * lj;
            Osm[(d0 + 0) * 130 + r0]     = oacc[mt][nt][0] * inv[mt * 2];
            Osm[(d0 + 1) * 130 + r0]     = oacc[mt][nt][1] * inv[mt * 2];
            Osm[(d0 + 0) * 130 + r0 + 8] = oacc[mt][nt][2] * inv[mt * 2 + 1];
            Osm[(d0 + 1) * 130 + r0 + 8] = oacc[mt][nt][3] * inv[mt * 2 + 1];
        }
    }
    __syncthreads();
    for (int i = tid; i < 4096; i += 128) {
        int d = i >> 7, q = i & 127;
        Out[(size_t)d * S + q0 + q] = Osm[d * 130 + q];
    }
}

// ---------------- 3x3 conv as implicit GEMM on tf32 mma.sync ----------------
// grid (16 tiles of 16x16 px, 6 cog, 4 n), 256 threads (8 warps).
// M=32 co (2 m16), N=256 px (warp w owns rows 2w,2w+1 -> 4 n8 tiles), K=864.
// K staged per ci-group of 16: k_local = (kh*3+kw)*16 + ciL, 144 rows.
// patchF: 16 ci x 332 words (bank = 8*ciL + px, conflict-free B frags)
// Wsm: 144 k x 40 words  (bank = 8*kL + co, conflict-free A frags)
__global__ __launch_bounds__(256)
void conv_tc_kernel(const float* __restrict__ Zin, const float* __restrict__ hin,
                    const float* __restrict__ Wo, const float* __restrict__ bo,
                    float* __restrict__ out) {
    __shared__ uint32_t patchF[16 * 332];
    __shared__ uint32_t Wsm[144 * 40];

    int tid = threadIdx.x;
    int w = tid >> 5, lane = tid & 31;
    int lq = lane >> 2, l4 = lane & 3;
    int n = blockIdx.z, cog = blockIdx.y, tile = blockIdx.x;
    int ty0 = (tile >> 2) * 16, tx0 = (tile & 3) * 16;

    float oacc[2][4][4];
#pragma unroll
    for (int mt = 0; mt < 2; mt++)
#pragma unroll
        for (int nt = 0; nt < 4; nt++)
#pragma unroll
            for (int r = 0; r < 4; r++) oacc[mt][nt][r] = 0.f;

    for (int cig = 0; cig < 6; cig++) {
        __syncthreads();
        // stage input patch (18x18 with zero pad), fp32 -> tf32
        for (int l = tid; l < 16 * 324; l += 256) {
            int ci = l / 324, rem = l - ci * 324;
            int yy = rem / 18 + ty0 - 1, xx = rem % 18 + tx0 - 1;
            float v = 0.f;
            if (yy >= 0 && yy < HH && xx >= 0 && xx < WW) {
                int cg = cig * 16 + ci;
                v = (cg < 32) ? Zin[((size_t)n * 32 + cg) * S + yy * WW + xx]
                              : hin[((size_t)n * 64 + (cg - 32)) * S + yy * WW + xx];
            }
            patchF[ci * 332 + rem] = f2tf32(v);
        }
        // stage weights: Wsm[kL*40 + co], kL = khkw*16 + ciL
        for (int l = tid; l < 144 * 32; l += 256) {
            int co = l & 31, kl = l >> 5;
            int khkw = kl >> 4, ciL = kl & 15;
            float v = Wo[(((size_t)cog * 32 + co) * 96 + cig * 16 + ciL) * 9 + khkw];
            Wsm[kl * 40 + co] = f2tf32(v);
        }
        __syncthreads();

        for (int khkw = 0; khkw < 9; khkw++) {
            int kh = khkw / 3, kw = khkw - 3 * kh;
#pragma unroll
            for (int c8 = 0; c8 < 2; c8++) {
                int kb = khkw * 16 + c8 * 8;
                uint32_t a[2][4];
#pragma unroll
                for (int mt = 0; mt < 2; mt++) {
                    int co0 = mt * 16 + lq;
                    a[mt][0] = Wsm[(kb + l4) * 40 + co0];
                    a[mt][1] = Wsm[(kb + l4) * 40 + co0 + 8];
                    a[mt][2] = Wsm[(kb + l4 + 4) * 40 + co0];
                    a[mt][3] = Wsm[(kb + l4 + 4) * 40 + co0 + 8];
                }
#pragma unroll
                for (int nt = 0; nt < 4; nt++) {
                    int py = 2 * w + (nt >> 1), pxx = (nt & 1) * 8 + lq;
                    int off = (py + kh) * 18 + pxx + kw;
                    uint32_t b0 = patchF[(c8 * 8 + l4) * 332 + off];
                    uint32_t b1 = patchF[(c8 * 8 + l4 + 4) * 332 + off];
                    mma1688t(oacc[0][nt], a[0], b0, b1);
                    mma1688t(oacc[1][nt], a[1], b0, b1);
                }
            }
        }
    }

    // epilogue: C[row=co_local, col=pixel]; c0,c1 cols 2*l4, 2*l4+1; c2,c3 rows +8
#pragma unroll
    for (int mt = 0; mt < 2; mt++) {
        int coA = cog * 32 + mt * 16 + lq;
        int coB = coA + 8;
        float bA = bo[coA], bB = bo[coB];
        size_t baseA = ((size_t)n * 192 + coA) * S;
        size_t baseB = ((size_t)n * 192 + coB) * S;
#pragma unroll
        for (int nt = 0; nt < 4; nt++) {
            int y = ty0 + 2 * w + (nt >> 1);
            int x = tx0 + (nt & 1) * 8 + 2 * l4;
            float2 vA = make_float2(oacc[mt][nt][0] + bA, oacc[mt][nt][1] + bA);
            float2 vB = make_float2(oacc[mt][nt][2] + bB, oacc[mt][nt][3] + bB);
            *(float2*)&out[baseA + y * WW + x] = vA;
            *(float2*)&out[baseB + y * WW + x] = vB;
        }
    }
}

// ---------------- gates ----------------
__global__ __launch_bounds__(256)
void gates_kernel(const float* __restrict__ conv, const float* __restrict__ m,
                  float* __restrict__ out) {
    int idx = blockIdx.x * 256 + threadIdx.x;
    int n = idx >> 18;
    int rem = idx & 262143;
    size_t base = (size_t)n * 192 * S;
    float iv = conv[base + rem];
    float gv = conv[base + 64 * S + rem];
    float ov = conv[base + 128 * S + rem];
    float mi = m[idx];
    float si = 1.0f / (1.0f + __expf(-iv));
    float gg = tanhf(gv);
    float so = 1.0f / (1.0f + __expf(-ov));
    float mn = si * gg + (1.0f - si) * mi;
    float hn = so * mn;
    out[idx] = hn;
    out[1048576 + idx] = mn;
}

// ---------------- launch ----------------
extern "C" void kernel_launch(void* const* d_in, const int* in_sizes, int n_in,
                              void* d_out, int out_size) {
    const float* h  = (const float*)d_in[0];
    const float* m  = (const float*)d_in[1];
    const float* Wh = (const float*)d_in[2];
    const float* bh = (const float*)d_in[3];
    const float* Wm = (const float*)d_in[4];
    const float* bm = (const float*)d_in[5];
    const float* Wz = (const float*)d_in[6];
    const float* bz = (const float*)d_in[7];
    const float* Wo = (const float*)d_in[8];
    const float* bo = (const float*)d_in[9];
    float* out = (float*)d_out;

    float *pHqkv, *pMkv, *pZ2, *pZp, *pConv;
    cudaGetSymbolAddress((void**)&pHqkv, g_hqkv);
    cudaGetSymbolAddress((void**)&pMkv,  g_mkv);
    cudaGetSymbolAddress((void**)&pZ2,   g_Z2);
    cudaGetSymbolAddress((void**)&pZp,   g_Zp);
    cudaGetSymbolAddress((void**)&pConv, g_conv);

    proj_kernel<64, 96><<<dim3(32, 3, 4), 128>>>(h, Wh, bh, pHqkv);
    proj_kernel<64, 64><<<dim3(32, 2, 4), 128>>>(m, Wm, bm, pMkv);
    attn_mma_kernel<<<dim3(32, 2, 4), 128>>>(pHqkv, pMkv, pZ2);
    proj_kernel<64, 32><<<dim3(32, 1, 4), 128>>>(pZ2, Wz, bz, pZp);
    conv_tc_kernel<<<dim3(16, 6, 4), 256>>>(pZp, h, Wo, bo, pConv);
    gates_kernel<<<4096, 256>>>(pConv, m, out);
}

// round 7
// speedup vs baseline: 3.5816x; 1.4031x over previous
#include <cuda_runtime.h>
#include <cuda_bf16.h>
#include <cstdint>

#define S 4096
#define HH 64
#define WW 64

// ---------------- scratch (no allocations allowed) ----------------
__device__ float g_hqkv[4 * 96 * S];
__device__ float g_mkv [4 * 64 * S];
__device__ float g_Z2  [4 * 64 * S];
__device__ float g_Zp  [4 * 32 * S];
__device__ float g_conv[4 * 192 * S];

// ---------------- mma.sync helpers ----------------
__device__ __forceinline__ void mma16816(float* c, const uint32_t* a, uint32_t b0, uint32_t b1) {
    asm volatile(
        "mma.sync.aligned.m16n8k16.row.col.f32.bf16.bf16.f32 "
        "{%0,%1,%2,%3}, {%4,%5,%6,%7}, {%8,%9}, {%0,%1,%2,%3};"
        : "+f"(c[0]), "+f"(c[1]), "+f"(c[2]), "+f"(c[3])
        : "r"(a[0]), "r"(a[1]), "r"(a[2]), "r"(a[3]), "r"(b0), "r"(b1));
}
__device__ __forceinline__ void mma1688t(float* c, const uint32_t* a, uint32_t b0, uint32_t b1) {
    asm volatile(
        "mma.sync.aligned.m16n8k8.row.col.f32.tf32.tf32.f32 "
        "{%0,%1,%2,%3}, {%4,%5,%6,%7}, {%8,%9}, {%0,%1,%2,%3};"
        : "+f"(c[0]), "+f"(c[1]), "+f"(c[2]), "+f"(c[3])
        : "r"(a[0]), "r"(a[1]), "r"(a[2]), "r"(a[3]), "r"(b0), "r"(b1));
}
__device__ __forceinline__ uint32_t packbf(float lo, float hi) {
    uint32_t r;
    asm("cvt.rn.bf16x2.f32 %0, %2, %1;" : "=r"(r) : "f"(lo), "f"(hi));
    return r;
}
__device__ __forceinline__ uint32_t f2tf32(float f) {
    uint32_t r;
    asm("cvt.rna.tf32.f32 %0, %1;" : "=r"(r) : "f"(f));
    return r;
}

// ---------------- 1x1 projection as tf32 GEMM ----------------
// Per CTA: C[32 co][128 s] = W[32,64] x X[64][128s] (+bias).
// 128 threads = 4 warps; warp w owns s-cols [32w, 32w+32) as 4 n8 tiles; M=32 = 2 m16.
// smem: Xs[64][136] tf32 (conflict-free B frags), Ws2[64][40] (conflict-free A frags).
#define PRJ_XS_ST 136
#define PRJ_WS_ST 40

__device__ __forceinline__ void proj_gemm_body(
    uint32_t* Xs, uint32_t* Ws2,
    const float* Xg, const float* Wg, const float* bg,
    float* outg, int s0)
{
    int tid = threadIdx.x;
    int w = tid >> 5, lane = tid & 31;
    int lq = lane >> 2, l4 = lane & 3;

    // stage X[64][128] (coalesced), convert tf32
    for (int i = tid; i < 64 * 128; i += 128) {
        int ci = i >> 7, sl = i & 127;
        Xs[ci * PRJ_XS_ST + sl] = f2tf32(Xg[(size_t)ci * S + s0 + sl]);
    }
    // stage W[32][64] -> Ws2[ci][co]
    for (int i = tid; i < 32 * 64; i += 128) {
        int co = i >> 6, ci = i & 63;
        Ws2[ci * PRJ_WS_ST + co] = f2tf32(Wg[co * 64 + ci]);
    }
    __syncthreads();

    float oacc[2][4][4];
#pragma unroll
    for (int mt = 0; mt < 2; mt++)
#pragma unroll
        for (int nt = 0; nt < 4; nt++)
#pragma unroll
            for (int r = 0; r < 4; r++) oacc[mt][nt][r] = 0.f;

#pragma unroll
    for (int kb8 = 0; kb8 < 8; kb8++) {
        int kb = kb8 * 8;
        uint32_t a[2][4];
#pragma unroll
        for (int mt = 0; mt < 2; mt++) {
            int co0 = mt * 16 + lq;
            a[mt][0] = Ws2[(kb + l4) * PRJ_WS_ST + co0];
            a[mt][1] = Ws2[(kb + l4) * PRJ_WS_ST + co0 + 8];
            a[mt][2] = Ws2[(kb + l4 + 4) * PRJ_WS_ST + co0];
            a[mt][3] = Ws2[(kb + l4 + 4) * PRJ_WS_ST + co0 + 8];
        }
#pragma unroll
        for (int nt = 0; nt < 4; nt++) {
            int scol = w * 32 + nt * 8 + lq;
            uint32_t b0 = Xs[(kb + l4) * PRJ_XS_ST + scol];
            uint32_t b1 = Xs[(kb + l4 + 4) * PRJ_XS_ST + scol];
            mma1688t(oacc[0][nt], a[0], b0, b1);
            mma1688t(oacc[1][nt], a[1], b0, b1);
        }
    }

    // epilogue: row = co (lq / lq+8), cols 2*l4, 2*l4+1
#pragma unroll
    for (int mt = 0; mt < 2; mt++) {
        int coA = mt * 16 + lq, coB = coA + 8;
        float bA = bg[coA], bB = bg[coB];
#pragma unroll
        for (int nt = 0; nt < 4; nt++) {
            int x = s0 + w * 32 + nt * 8 + 2 * l4;
            *(float2*)&outg[(size_t)coA * S + x] = make_float2(oacc[mt][nt][0] + bA, oacc[mt][nt][1] + bA);
            *(float2*)&outg[(size_t)coB * S + x] = make_float2(oacc[mt][nt][2] + bB, oacc[mt][nt][3] + bB);
        }
    }
}

// merged h-proj (96 co) + m-proj (64 co): blockIdx.y 0..4
__global__ __launch_bounds__(128)
void projhm_kernel(const float* __restrict__ h, const float* __restrict__ Wh,
                   const float* __restrict__ bh, float* __restrict__ hqkv,
                   const float* __restrict__ m, const float* __restrict__ Wm,
                   const float* __restrict__ bm, float* __restrict__ mkv) {
    __shared__ uint32_t Xs[64 * PRJ_XS_ST];
    __shared__ uint32_t Ws2[64 * PRJ_WS_ST];
    int n = blockIdx.z, y = blockIdx.y;
    int s0 = blockIdx.x * 128;
    if (y < 3) {
        int co0 = y * 32;
        proj_gemm_body(Xs, Ws2, h + (size_t)n * 64 * S, Wh + (size_t)co0 * 64, bh + co0,
                       hqkv + ((size_t)n * 96 + co0) * S, s0);
    } else {
        int co0 = (y - 3) * 32;
        proj_gemm_body(Xs, Ws2, m + (size_t)n * 64 * S, Wm + (size_t)co0 * 64, bm + co0,
                       mkv + ((size_t)n * 64 + co0) * S, s0);
    }
}

__global__ __launch_bounds__(128)
void projz_kernel(const float* __restrict__ Z2, const float* __restrict__ Wz,
                  const float* __restrict__ bz, float* __restrict__ Zp) {
    __shared__ uint32_t Xs[64 * PRJ_XS_ST];
    __shared__ uint32_t Ws2[64 * PRJ_WS_ST];
    int n = blockIdx.z;
    int s0 = blockIdx.x * 128;
    proj_gemm_body(Xs, Ws2, Z2 + (size_t)n * 64 * S, Wz, bz, Zp + (size_t)n * 32 * S, s0);
}

// ---------------- flash attention, software-pipelined double buffer ----------------
// grid (32 qtiles, 2 att, 4 n), 128 threads (4 warps), 128 queries/CTA.
// smem words: Qs 128x20 = 2560 | Kbuf[2] 64x20 = 1280 ea | Vbuf[2] 32x35 = 1120 ea
#define AQ_W   2560
#define AK_W   1280
#define AV_W   1120
#define A_TOT  (AQ_W + 2 * AK_W + 2 * AV_W)

__global__ __launch_bounds__(128)
void attn_mma_kernel(const float* __restrict__ hqkv, const float* __restrict__ mkv,
                     float* __restrict__ Z2) {
    __shared__ uint32_t smw[A_TOT];
    uint32_t* Qsw = smw;
    uint32_t* Kb0 = smw + AQ_W;
    uint32_t* Vb0 = smw + AQ_W + 2 * AK_W;
    __nv_bfloat16* Qh = (__nv_bfloat16*)Qsw;

    int tid = threadIdx.x;
    int w = tid >> 5, lane = tid & 31;
    int lq = lane >> 2, lj = lane & 3;
    int n = blockIdx.z, att = blockIdx.y;
    int q0 = blockIdx.x * 128;

    const float* Q = hqkv + (size_t)n * 96 * S;
    const float* K = (att == 0) ? hqkv + ((size_t)n * 96 + 32) * S
                                : mkv  + ((size_t)n * 64 +  0) * S;
    const float* V = (att == 0) ? hqkv + ((size_t)n * 96 + 64) * S
                                : mkv  + ((size_t)n * 64 + 32) * S;
    float* Out = Z2 + ((size_t)n * 64 + att * 32) * S;

    const float scale = 0.17677669529663687f;
    for (int i = tid; i < 4096; i += 128) {
        int d = i >> 7, q = i & 127;
        Qh[q * 40 + d] = __float2bfloat16(Q[(size_t)d * S + q0 + q] * scale);
    }
    __syncthreads();

    uint32_t qa[2][2][4];
#pragma unroll
    for (int mt = 0; mt < 2; mt++) {
        int r0 = 32 * w + 16 * mt + lq;
#pragma unroll
        for (int ks = 0; ks < 2; ks++) {
            qa[mt][ks][0] = Qsw[r0 * 20 + ks * 8 + lj];
            qa[mt][ks][1] = Qsw[(r0 + 8) * 20 + ks * 8 + lj];
            qa[mt][ks][2] = Qsw[r0 * 20 + ks * 8 + lj + 4];
            qa[mt][ks][3] = Qsw[(r0 + 8) * 20 + ks * 8 + lj + 4];
        }
    }

    float oacc[2][4][4];
#pragma unroll
    for (int mt = 0; mt < 2; mt++)
#pragma unroll
        for (int nt = 0; nt < 4; nt++)
#pragma unroll
            for (int r = 0; r < 4; r++) oacc[mt][nt][r] = 0.f;
    float l_acc[4] = {0.f, 0.f, 0.f, 0.f};

    // ---- prefetch chunk 0 into regs
    uint32_t kreg[8], vreg[8];
    {
#pragma unroll
        for (int j = 0; j < 8; j++) {
            int idx = j * 128 + tid;
            int k = idx & 63, dp = idx >> 6;
            float lo = K[(size_t)(2 * dp) * S + k];
            float hi = K[(size_t)(2 * dp + 1) * S + k];
            kreg[j] = packbf(lo, hi);
        }
#pragma unroll
        for (int j = 0; j < 8; j++) {
            int idx = j * 128 + tid;
            int d = idx >> 5, kp = idx & 31;
            float2 v2 = *(const float2*)&V[(size_t)d * S + 2 * kp];
            vreg[j] = packbf(v2.x, v2.y);
        }
    }

#pragma unroll 1
    for (int kt = 0; kt < 64; kt++) {
        uint32_t* Kbuf = Kb0 + (kt & 1) * AK_W;
        uint32_t* Vbuf = Vb0 + (kt & 1) * AV_W;
        // commit prefetched regs to this chunk's buffer
#pragma unroll
        for (int j = 0; j < 8; j++) {
            int idx = j * 128 + tid;
            Kbuf[(idx & 63) * 20 + (idx >> 6)] = kreg[j];
        }
#pragma unroll
        for (int j = 0; j < 8; j++) {
            int idx = j * 128 + tid;
            Vbuf[(idx >> 5) * 35 + (idx & 31)] = vreg[j];
        }
        __syncthreads();

        // prefetch next chunk while computing this one
        if (kt < 63) {
            int kb = (kt + 1) * 64;
#pragma unroll
            for (int j = 0; j < 8; j++) {
                int idx = j * 128 + tid;
                int k = idx & 63, dp = idx >> 6;
                float lo = K[(size_t)(2 * dp) * S + kb + k];
                float hi = K[(size_t)(2 * dp + 1) * S + kb + k];
                kreg[j] = packbf(lo, hi);
            }
#pragma unroll
            for (int j = 0; j < 8; j++) {
                int idx = j * 128 + tid;
                int d = idx >> 5, kp = idx & 31;
                float2 v2 = *(const float2*)&V[(size_t)d * S + kb + 2 * kp];
                vreg[j] = packbf(v2.x, v2.y);
            }
        }

        // ---- QK + softmax + pack P (B-frags shared across mt)
        uint32_t p[2][4][4];
        float rs[2][2] = {{0.f, 0.f}, {0.f, 0.f}};
#pragma unroll
        for (int nn = 0; nn < 8; nn++) {
            float c[2][4];
#pragma unroll
            for (int mt = 0; mt < 2; mt++)
#pragma unroll
                for (int r = 0; r < 4; r++) c[mt][r] = 0.f;
#pragma unroll
            for (int ks = 0; ks < 2; ks++) {
                int bw = (nn * 8 + lq) * 20 + ks * 8 + lj;
                uint32_t b0 = Kbuf[bw], b1 = Kbuf[bw + 4];
                mma16816(c[0], qa[0][ks], b0, b1);
                mma16816(c[1], qa[1][ks], b0, b1);
            }
            int kk = nn >> 1, half = (nn & 1) * 2;
#pragma unroll
            for (int mt = 0; mt < 2; mt++) {
                float e0 = __expf(c[mt][0]), e1 = __expf(c[mt][1]);
                float e2 = __expf(c[mt][2]), e3 = __expf(c[mt][3]);
                rs[mt][0] += e0 + e1; rs[mt][1] += e2 + e3;
                p[mt][kk][half + 0] = packbf(e0, e1);
                p[mt][kk][half + 1] = packbf(e2, e3);
            }
        }
#pragma unroll
        for (int mt = 0; mt < 2; mt++) {
            float r0 = rs[mt][0], r1 = rs[mt][1];
            r0 += __shfl_xor_sync(0xffffffffu, r0, 1);
            r0 += __shfl_xor_sync(0xffffffffu, r0, 2);
            r1 += __shfl_xor_sync(0xffffffffu, r1, 1);
            r1 += __shfl_xor_sync(0xffffffffu, r1, 2);
            l_acc[mt * 2 + 0] += r0;
            l_acc[mt * 2 + 1] += r1;
        }

        // ---- O += P @ V
#pragma unroll
        for (int nt = 0; nt < 4; nt++) {
#pragma unroll
            for (int kk = 0; kk < 4; kk++) {
                int bw = (nt * 8 + lq) * 35 + kk * 8 + lj;
                uint32_t b0 = Vbuf[bw], b1 = Vbuf[bw + 4];
                mma16816(oacc[0][nt], p[0][kk], b0, b1);
                mma16816(oacc[1][nt], p[1][kk], b0, b1);
            }
        }
    }

    // ---- epilogue: normalize, stage Osm[d][q] (stride 130), coalesced store
    __syncthreads();
    float* Osm = (float*)smw;
    float inv[4];
#pragma unroll
    for (int r = 0; r < 4; r++) inv[r] = 1.0f / l_acc[r];
#pragma unroll
    for (int mt = 0; mt < 2; mt++) {
        int r0 = 32 * w + 16 * mt + lq;
#pragma unroll
        for (int nt = 0; nt < 4; nt++) {
            int d0 = nt * 8 + 2 * lj;
            Osm[(d0 + 0) * 130 + r0]     = oacc[mt][nt][0] * inv[mt * 2];
            Osm[(d0 + 1) * 130 + r0]     = oacc[mt][nt][1] * inv[mt * 2];
            Osm[(d0 + 0) * 130 + r0 + 8] = oacc[mt][nt][2] * inv[mt * 2 + 1];
            Osm[(d0 + 1) * 130 + r0 + 8] = oacc[mt][nt][3] * inv[mt * 2 + 1];
        }
    }
    __syncthreads();
    for (int i = tid; i < 4096; i += 128) {
        int d = i >> 7, q = i & 127;
        Out[(size_t)d * S + q0 + q] = Osm[d * 130 + q];
    }
}

// ---------------- 3x3 conv as implicit GEMM on tf32 mma.sync (unchanged) ----------------
__global__ __launch_bounds__(256)
void conv_tc_kernel(const float* __restrict__ Zin, const float* __restrict__ hin,
                    const float* __restrict__ Wo, const float* __restrict__ bo,
                    float* __restrict__ out) {
    __shared__ uint32_t patchF[16 * 332];
    __shared__ uint32_t Wsm[144 * 40];

    int tid = threadIdx.x;
    int w = tid >> 5, lane = tid & 31;
    int lq = lane >> 2, l4 = lane & 3;
    int n = blockIdx.z, cog = blockIdx.y, tile = blockIdx.x;
    int ty0 = (tile >> 2) * 16, tx0 = (tile & 3) * 16;

    float oacc[2][4][4];
#pragma unroll
    for (int mt = 0; mt < 2; mt++)
#pragma unroll
        for (int nt = 0; nt < 4; nt++)
#pragma unroll
            for (int r = 0; r < 4; r++) oacc[mt][nt][r] = 0.f;

    for (int cig = 0; cig < 6; cig++) {
        __syncthreads();
        for (int l = tid; l < 16 * 324; l += 256) {
            int ci = l / 324, rem = l - ci * 324;
            int yy = rem / 18 + ty0 - 1, xx = rem % 18 + tx0 - 1;
            float v = 0.f;
            if (yy >= 0 && yy < HH && xx >= 0 && xx < WW) {
                int cg = cig * 16 + ci;
                v = (cg < 32) ? Zin[((size_t)n * 32 + cg) * S + yy * WW + xx]
                              : hin[((size_t)n * 64 + (cg - 32)) * S + yy * WW + xx];
            }
            patchF[ci * 332 + rem] = f2tf32(v);
        }
        for (int l = tid; l < 144 * 32; l += 256) {
            int co = l & 31, kl = l >> 5;
            int khkw = kl >> 4, ciL = kl & 15;
            float v = Wo[(((size_t)cog * 32 + co) * 96 + cig * 16 + ciL) * 9 + khkw];
            Wsm[kl * 40 + co] = f2tf32(v);
        }
        __syncthreads();

        for (int khkw = 0; khkw < 9; khkw++) {
            int kh = khkw / 3, kw = khkw - 3 * kh;
#pragma unroll
            for (int c8 = 0; c8 < 2; c8++) {
                int kb = khkw * 16 + c8 * 8;
                uint32_t a[2][4];
#pragma unroll
                for (int mt = 0; mt < 2; mt++) {
                    int co0 = mt * 16 + lq;
                    a[mt][0] = Wsm[(kb + l4) * 40 + co0];
                    a[mt][1] = Wsm[(kb + l4) * 40 + co0 + 8];
                    a[mt][2] = Wsm[(kb + l4 + 4) * 40 + co0];
                    a[mt][3] = Wsm[(kb + l4 + 4) * 40 + co0 + 8];
                }
#pragma unroll
                for (int nt = 0; nt < 4; nt++) {
                    int py = 2 * w + (nt >> 1), pxx = (nt & 1) * 8 + lq;
                    int off = (py + kh) * 18 + pxx + kw;
                    uint32_t b0 = patchF[(c8 * 8 + l4) * 332 + off];
                    uint32_t b1 = patchF[(c8 * 8 + l4 + 4) * 332 + off];
                    mma1688t(oacc[0][nt], a[0], b0, b1);
                    mma1688t(oacc[1][nt], a[1], b0, b1);
                }
            }
        }
    }

#pragma unroll
    for (int mt = 0; mt < 2; mt++) {
        int coA = cog * 32 + mt * 16 + lq;
        int coB = coA + 8;
        float bA = bo[coA], bB = bo[coB];
        size_t baseA = ((size_t)n * 192 + coA) * S;
        size_t baseB = ((size_t)n * 192 + coB) * S;
#pragma unroll
        for (int nt = 0; nt < 4; nt++) {
            int y = ty0 + 2 * w + (nt >> 1);
            int x = tx0 + (nt & 1) * 8 + 2 * l4;
            *(float2*)&out[baseA + y * WW + x] = make_float2(oacc[mt][nt][0] + bA, oacc[mt][nt][1] + bA);
            *(float2*)&out[baseB + y * WW + x] = make_float2(oacc[mt][nt][2] + bB, oacc[mt][nt][3] + bB);
        }
    }
}

// ---------------- gates (float4) ----------------
__global__ __launch_bounds__(256)
void gates_kernel(const float* __restrict__ conv, const float* __restrict__ m,
                  float* __restrict__ out) {
    int idx4 = blockIdx.x * 256 + threadIdx.x;     // over 262144 float4 groups
    int n = idx4 >> 16;                            // 65536 float4 per n
    int rem = (idx4 & 65535) * 4;
    size_t base = (size_t)n * 192 * S;
    float4 iv = *(const float4*)&conv[base + rem];
    float4 gv = *(const float4*)&conv[base + 64 * S + rem];
    float4 ov = *(const float4*)&conv[base + 128 * S + rem];
    float4 mi = *(const float4*)&m[(size_t)n * 64 * S + rem];
    float4 hn, mn;
    {
        float si = 1.0f / (1.0f + __expf(-iv.x)), gg = tanhf(gv.x), so = 1.0f / (1.0f + __expf(-ov.x));
        mn.x = si * gg + (1.0f - si) * mi.x; hn.x = so * mn.x;
        si = 1.0f / (1.0f + __expf(-iv.y)); gg = tanhf(gv.y); so = 1.0f / (1.0f + __expf(-ov.y));
        mn.y = si * gg + (1.0f - si) * mi.y; hn.y = so * mn.y;
        si = 1.0f / (1.0f + __expf(-iv.z)); gg = tanhf(gv.z); so = 1.0f / (1.0f + __expf(-ov.z));
        mn.z = si * gg + (1.0f - si) * mi.z; hn.z = so * mn.z;
        si = 1.0f / (1.0f + __expf(-iv.w)); gg = tanhf(gv.w); so = 1.0f / (1.0f + __expf(-ov.w));
        mn.w = si * gg + (1.0f - si) * mi.w; hn.w = so * mn.w;
    }
    size_t oidx = (size_t)n * 64 * S + rem;
    *(float4*)&out[oidx] = hn;
    *(float4*)&out[1048576 + oidx] = mn;
}

// ---------------- launch ----------------
extern "C" void kernel_launch(void* const* d_in, const int* in_sizes, int n_in,
                              void* d_out, int out_size) {
    const float* h  = (const float*)d_in[0];
    const float* m  = (const float*)d_in[1];
    const float* Wh = (const float*)d_in[2];
    const float* bh = (const float*)d_in[3];
    const float* Wm = (const float*)d_in[4];
    const float* bm = (const float*)d_in[5];
    const float* Wz = (const float*)d_in[6];
    const float* bz = (const float*)d_in[7];
    const float* Wo = (const float*)d_in[8];
    const float* bo = (const float*)d_in[9];
    float* out = (float*)d_out;

    float *pHqkv, *pMkv, *pZ2, *pZp, *pConv;
    cudaGetSymbolAddress((void**)&pHqkv, g_hqkv);
    cudaGetSymbolAddress((void**)&pMkv,  g_mkv);
    cudaGetSymbolAddress((void**)&pZ2,   g_Z2);
    cudaGetSymbolAddress((void**)&pZp,   g_Zp);
    cudaGetSymbolAddress((void**)&pConv, g_conv);

    projhm_kernel<<<dim3(32, 5, 4), 128>>>(h, Wh, bh, pHqkv, m, Wm, bm, pMkv);
    attn_mma_kernel<<<dim3(32, 2, 4), 128>>>(pHqkv, pMkv, pZ2);
    projz_kernel<<<dim3(32, 1, 4), 128>>>(pZ2, Wz, bz, pZp);
    conv_tc_kernel<<<dim3(16, 6, 4), 256>>>(pZp, h, Wo, bo, pConv);
    gates_kernel<<<1024, 256>>>(pConv, m, out);
}